// round 4
// baseline (speedup 1.0000x reference)
#include <cuda_runtime.h>
#include <cstdint>

// Problem constants (hardcoded shapes from reference)
#define KCODES     512
#define DCH        16
#define NPTS       262144          // B*T*H*W = 2*32*64*64
#define CH_STRIDE  131072          // T*H*W
#define BATCH_STRIDE 2097152       // C*CH_STRIDE
#define BLOCK      256
#define GRID       256             // NPTS / 4 / BLOCK
#define QOUT_ELEMS 4194304
#define ENC_OFF    4194305         // 1 (loss) + QOUT_ELEMS

__device__ float g_part[GRID];

// ---- packed f32x2 helpers (sm_100+) ----
static __device__ __forceinline__ unsigned long long fma2(unsigned long long a,
                                                          unsigned long long b,
                                                          unsigned long long c) {
    unsigned long long d;
    asm("fma.rn.f32x2 %0, %1, %2, %3;" : "=l"(d) : "l"(a), "l"(b), "l"(c));
    return d;
}
static __device__ __forceinline__ unsigned long long add2(unsigned long long a,
                                                          unsigned long long b) {
    unsigned long long d;
    asm("add.rn.f32x2 %0, %1, %2;" : "=l"(d) : "l"(a), "l"(b));
    return d;
}
static __device__ __forceinline__ unsigned long long pack2(float lo, float hi) {
    unsigned long long r;
    unsigned int a = __float_as_uint(lo), b = __float_as_uint(hi);
    asm("mov.b64 %0, {%1, %2};" : "=l"(r) : "r"(a), "r"(b));
    return r;
}
static __device__ __forceinline__ void unpack2(unsigned long long v, float& lo, float& hi) {
    unsigned int a, b;
    asm("mov.b64 {%0, %1}, %2;" : "=r"(a), "=r"(b) : "l"(v));
    lo = __uint_as_float(a);
    hi = __uint_as_float(b);
}
// strict rounded ops (block mul+add -> fma contraction)
static __device__ __forceinline__ float mul_rn(float a, float b) {
    float r;
    asm("mul.rn.f32 %0, %1, %2;" : "=f"(r) : "f"(a), "f"(b));
    return r;
}
static __device__ __forceinline__ float add_rn(float a, float b) {
    float r;
    asm("add.rn.f32 %0, %1, %2;" : "=f"(r) : "f"(a), "f"(b));
    return r;
}

// LLVM/NEON VF=4 vectorized sum-of-squares of 16 contiguous elements:
//   m_k = round(v_k * v_k)
//   lane_j = ((m_j + m_{j+4}) + m_{j+8}) + m_{j+12}      (j = 0..3)
//   sum    = (l0 + l1) + (l2 + l3)     <- faddp,faddp lowering of
//                                         llvm.vector.reduce.fadd
static __device__ __forceinline__ float sumsq16_neon(const float* v) {
    float l[4];
    #pragma unroll
    for (int j = 0; j < 4; j++) {
        float a = mul_rn(v[j], v[j]);
        a = add_rn(a, mul_rn(v[j + 4],  v[j + 4]));
        a = add_rn(a, mul_rn(v[j + 8],  v[j + 8]));
        a = add_rn(a, mul_rn(v[j + 12], v[j + 12]));
        l[j] = a;
    }
    return add_rn(add_rn(l[0], l[1]), add_rn(l[2], l[3]));
}

// Shared memory layout:
//   [0      .. 65536)  : sEb  [256 code-pairs][16 d][2 codes]  u64 broadcast pairs (E,E)
//   [65536  .. 69632)  : sE2  [256 code-pairs][2 codes]        u64 broadcast pairs (e2,e2)
//   [69632  .. 70656)  : sred [256] float  (loss block reduce)
#define SMEM_BYTES 70656

__global__ __launch_bounds__(BLOCK, 2)
void vq_main_kernel(const float* __restrict__ x, const float* __restrict__ E,
                    float* __restrict__ out) {
    extern __shared__ unsigned char sm[];
    unsigned long long* sEb = (unsigned long long*)sm;
    unsigned long long* sE2 = (unsigned long long*)(sm + 65536);
    float*              sred = (float*)(sm + 69632);

    const int tid = threadIdx.x;

    // ---- cooperative smem fill: thread t owns codes 2t, 2t+1 ----
    {
        const float* e0 = E + (2 * tid) * DCH;
        float va[16], vb[16];
        #pragma unroll
        for (int d = 0; d < DCH; d++) {
            float a = e0[d];
            float b = e0[DCH + d];
            va[d] = a; vb[d] = b;
            sEb[(tid * 16 + d) * 2 + 0] = pack2(a, a);
            sEb[(tid * 16 + d) * 2 + 1] = pack2(b, b);
        }
        float ea = sumsq16_neon(va);
        float eb = sumsq16_neon(vb);
        sE2[tid * 2 + 0] = pack2(ea, ea);
        sE2[tid * 2 + 1] = pack2(eb, eb);
    }
    __syncthreads();

    // ---- this thread handles 4 consecutive points ----
    const int gt = blockIdx.x * BLOCK + tid;
    const long long n0 = (long long)gt * 4;
    const int b = (int)(n0 >> 17);          // / CH_STRIDE (pow2)
    const int r = (int)(n0 & 131071);       // % CH_STRIDE

    const float* xp = x + (size_t)b * BATCH_STRIDE + r;

    unsigned long long xx01[16], xx23[16];
    float p0[16], p1[16], p2[16], p3[16];   // per-point channel vectors
    #pragma unroll
    for (int c = 0; c < 16; c++) {
        float4 v = *(const float4*)(xp + (size_t)c * CH_STRIDE);
        xx01[c] = pack2(v.x, v.y);
        xx23[c] = pack2(v.z, v.w);
        p0[c] = v.x; p1[c] = v.y; p2[c] = v.z; p3[c] = v.w;
    }
    const float x2_0 = sumsq16_neon(p0);
    const float x2_1 = sumsq16_neon(p1);
    const float x2_2 = sumsq16_neon(p2);
    const float x2_3 = sumsq16_neon(p3);
    const unsigned long long x2p01 = pack2(x2_0, x2_1);
    const unsigned long long x2p23 = pack2(x2_2, x2_3);
    const unsigned long long neg2  = pack2(-2.f, -2.f);

    float best0 = 3.402823466e38f, best1 = best0, best2 = best0, best3 = best0;
    int bi0 = 0, bi1 = 0, bi2 = 0, bi3 = 0;

    // encodings zero-fill: warp-cooperative, interleaved with compute.
    // Warp (global id w) owns rows [w*128, w*128+128) => 65536 floats.
    const int lane  = tid & 31;
    const int warpg = gt >> 5;
    float* ez = out + ENC_OFF + (size_t)warpg * 65536 + lane;  // 4B-aligned only

    #pragma unroll 1
    for (int j = 0; j < 256; j++) {
        const ulonglong2* ep = (const ulonglong2*)(sEb + j * 32);
        unsigned long long a0 = 0, a1 = 0, a2 = 0, a3 = 0;
        #pragma unroll
        for (int d = 0; d < 16; d++) {
            ulonglong2 e = ep[d];            // (dup(E[2j][d]), dup(E[2j+1][d]))
            a0 = fma2(xx01[d], e.x, a0);     // dot, code 2j,   pts 0,1
            a1 = fma2(xx23[d], e.x, a1);     // dot, code 2j,   pts 2,3
            a2 = fma2(xx01[d], e.y, a2);     // dot, code 2j+1, pts 0,1
            a3 = fma2(xx23[d], e.y, a3);     // dot, code 2j+1, pts 2,3
        }
        ulonglong2 e2 = ((const ulonglong2*)sE2)[j];
        // s = round(round(x2 + e2) - 2*dot)   -- replicates reference rounding
        unsigned long long s0 = fma2(neg2, a0, add2(x2p01, e2.x));
        unsigned long long s1 = fma2(neg2, a1, add2(x2p23, e2.x));
        unsigned long long s2 = fma2(neg2, a2, add2(x2p01, e2.y));
        unsigned long long s3 = fma2(neg2, a3, add2(x2p23, e2.y));

        const int k0 = 2 * j, k1 = 2 * j + 1;
        float f0, f1;
        unpack2(s0, f0, f1);
        if (f0 < best0) { best0 = f0; bi0 = k0; }
        if (f1 < best1) { best1 = f1; bi1 = k0; }
        unpack2(s1, f0, f1);
        if (f0 < best2) { best2 = f0; bi2 = k0; }
        if (f1 < best3) { best3 = f1; bi3 = k0; }
        unpack2(s2, f0, f1);
        if (f0 < best0) { best0 = f0; bi0 = k1; }
        if (f1 < best1) { best1 = f1; bi1 = k1; }
        unpack2(s3, f0, f1);
        if (f0 < best2) { best2 = f0; bi2 = k1; }
        if (f1 < best3) { best3 = f1; bi3 = k1; }

        // interleaved zero-fill: 8 x 128B coalesced STG.32 per iter
        #pragma unroll
        for (int u = 0; u < 8; u++) ez[j * 256 + u * 32] = 0.f;
    }

    // order zeros (cross-lane) before one-hot writes
    __syncwarp();
    {
        float* enc = out + ENC_OFF;
        enc[(size_t)(n0 + 0) * KCODES + bi0] = 1.0f;
        enc[(size_t)(n0 + 1) * KCODES + bi1] = 1.0f;
        enc[(size_t)(n0 + 2) * KCODES + bi2] = 1.0f;
        enc[(size_t)(n0 + 3) * KCODES + bi3] = 1.0f;
    }

    // ---- q_out (straight-through: x + (q - x)) + loss partial ----
    float* qbase = out + 1 + (size_t)b * BATCH_STRIDE + r;
    const float* E0 = E + bi0 * DCH;
    const float* E1 = E + bi1 * DCH;
    const float* E2 = E + bi2 * DCH;
    const float* E3 = E + bi3 * DCH;
    float ls = 0.f;
    #pragma unroll
    for (int c = 0; c < 16; c++) {
        float q0 = __ldg(E0 + c), q1 = __ldg(E1 + c), q2 = __ldg(E2 + c), q3 = __ldg(E3 + c);
        float xa = p0[c], xb = p1[c], xc = p2[c], xd = p3[c];
        float d0 = q0 - xa, d1 = q1 - xb, d2 = q2 - xc, d3 = q3 - xd;
        ls = fmaf(d0, d0, ls);
        ls = fmaf(d1, d1, ls);
        ls = fmaf(d2, d2, ls);
        ls = fmaf(d3, d3, ls);
        float* qo = qbase + (size_t)c * CH_STRIDE;   // 4B-aligned only -> scalar stores
        qo[0] = xa + d0;
        qo[1] = xb + d1;
        qo[2] = xc + d2;
        qo[3] = xd + d3;
    }

    // deterministic block reduction of loss partials
    sred[tid] = ls;
    __syncthreads();
    #pragma unroll
    for (int s = 128; s > 0; s >>= 1) {
        if (tid < s) sred[tid] += sred[tid + s];
        __syncthreads();
    }
    if (tid == 0) g_part[blockIdx.x] = sred[0];
}

__global__ void vq_finish_kernel(float* __restrict__ out) {
    __shared__ float sr[GRID];
    int t = threadIdx.x;
    sr[t] = g_part[t];
    __syncthreads();
    #pragma unroll
    for (int s = GRID / 2; s > 0; s >>= 1) {
        if (t < s) sr[t] += sr[t + s];
        __syncthreads();
    }
    if (t == 0) {
        float m = sr[0] / 4194304.0f;      // mean over N*D
        out[0] = m + 0.25f * m;            // q_latent + BETA * e_latent (equal forward values)
    }
}

extern "C" void kernel_launch(void* const* d_in, const int* in_sizes, int n_in,
                              void* d_out, int out_size) {
    const float* x = (const float*)d_in[0];
    const float* E = (const float*)d_in[1];
    if (n_in >= 2 && in_sizes[0] == KCODES * DCH) {  // safety if metadata order differs
        const float* t = x; x = E; E = t;
    }
    float* out = (float*)d_out;

    cudaFuncSetAttribute(vq_main_kernel,
                         cudaFuncAttributeMaxDynamicSharedMemorySize, SMEM_BYTES);
    vq_main_kernel<<<GRID, BLOCK, SMEM_BYTES>>>(x, E, out);
    vq_finish_kernel<<<1, GRID>>>(out);
}

// round 5
// speedup vs baseline: 1.0189x; 1.0189x over previous
#include <cuda_runtime.h>
#include <cstdint>

// Problem constants (hardcoded shapes from reference)
#define KCODES     512
#define DCH        16
#define NPTS       262144          // B*T*H*W = 2*32*64*64
#define CH_STRIDE  131072          // T*H*W
#define BATCH_STRIDE 2097152       // C*CH_STRIDE
#define BLOCK      256
#define GRID       256             // NPTS / 4 / BLOCK
#define QOUT_ELEMS 4194304
#define ENC_OFF    4194305         // 1 (loss) + QOUT_ELEMS

__device__ float g_part[GRID];

// ---- packed f32x2 helpers (sm_100+) ----
static __device__ __forceinline__ unsigned long long fma2(unsigned long long a,
                                                          unsigned long long b,
                                                          unsigned long long c) {
    unsigned long long d;
    asm("fma.rn.f32x2 %0, %1, %2, %3;" : "=l"(d) : "l"(a), "l"(b), "l"(c));
    return d;
}
static __device__ __forceinline__ unsigned long long add2(unsigned long long a,
                                                          unsigned long long b) {
    unsigned long long d;
    asm("add.rn.f32x2 %0, %1, %2;" : "=l"(d) : "l"(a), "l"(b));
    return d;
}
static __device__ __forceinline__ unsigned long long pack2(float lo, float hi) {
    unsigned long long r;
    unsigned int a = __float_as_uint(lo), b = __float_as_uint(hi);
    asm("mov.b64 %0, {%1, %2};" : "=l"(r) : "r"(a), "r"(b));
    return r;
}
static __device__ __forceinline__ void unpack2(unsigned long long v, float& lo, float& hi) {
    unsigned int a, b;
    asm("mov.b64 {%0, %1}, %2;" : "=r"(a), "=r"(b) : "l"(v));
    lo = __uint_as_float(a);
    hi = __uint_as_float(b);
}
// strict rounded ops (block mul+add -> fma contraction)
static __device__ __forceinline__ float mul_rn(float a, float b) {
    float r;
    asm("mul.rn.f32 %0, %1, %2;" : "=f"(r) : "f"(a), "f"(b));
    return r;
}
static __device__ __forceinline__ float add_rn(float a, float b) {
    float r;
    asm("add.rn.f32 %0, %1, %2;" : "=f"(r) : "f"(a), "f"(b));
    return r;
}
// streaming (evict-first) stores for write-once data
static __device__ __forceinline__ void stcs(float* p, float v) {
    asm volatile("st.global.cs.f32 [%0], %1;" :: "l"(p), "f"(v) : "memory");
}

// LLVM/NEON VF=4 vectorized sum-of-squares of 16 contiguous elements:
//   m_k = round(v_k * v_k)
//   lane_j = ((m_j + m_{j+4}) + m_{j+8}) + m_{j+12}      (j = 0..3)
//   sum    = (l0 + l1) + (l2 + l3)     <- faddp,faddp lowering
// (DO NOT CHANGE: this exact rounding tree is what makes argmin bit-match.)
static __device__ __forceinline__ float sumsq16_neon(const float* v) {
    float l[4];
    #pragma unroll
    for (int j = 0; j < 4; j++) {
        float a = mul_rn(v[j], v[j]);
        a = add_rn(a, mul_rn(v[j + 4],  v[j + 4]));
        a = add_rn(a, mul_rn(v[j + 8],  v[j + 8]));
        a = add_rn(a, mul_rn(v[j + 12], v[j + 12]));
        l[j] = a;
    }
    return add_rn(add_rn(l[0], l[1]), add_rn(l[2], l[3]));
}

// Shared memory layout:
//   [0      .. 65536)  : sEb  [256 code-pairs][16 d][2 codes]  u64 broadcast pairs (E,E)
//   [65536  .. 69632)  : sE2  [256 code-pairs][2 codes]        u64 broadcast pairs (e2,e2)
//   [69632  .. 70656)  : sred [256] float  (loss block reduce)
#define SMEM_BYTES 70656

__global__ __launch_bounds__(BLOCK, 2)
void vq_main_kernel(const float* __restrict__ x, const float* __restrict__ E,
                    float* __restrict__ out) {
    extern __shared__ unsigned char sm[];
    unsigned long long* sEb = (unsigned long long*)sm;
    unsigned long long* sE2 = (unsigned long long*)(sm + 65536);
    float*              sred = (float*)(sm + 69632);

    const int tid = threadIdx.x;

    // ---- cooperative smem fill: thread t owns codes 2t, 2t+1 ----
    {
        const float* e0 = E + (2 * tid) * DCH;
        float va[16], vb[16];
        #pragma unroll
        for (int d = 0; d < DCH; d++) {
            float a = e0[d];
            float b = e0[DCH + d];
            va[d] = a; vb[d] = b;
            sEb[(tid * 16 + d) * 2 + 0] = pack2(a, a);
            sEb[(tid * 16 + d) * 2 + 1] = pack2(b, b);
        }
        float ea = sumsq16_neon(va);
        float eb = sumsq16_neon(vb);
        sE2[tid * 2 + 0] = pack2(ea, ea);
        sE2[tid * 2 + 1] = pack2(eb, eb);
    }
    __syncthreads();

    // ---- this thread handles 4 consecutive points ----
    const int gt = blockIdx.x * BLOCK + tid;
    const long long n0 = (long long)gt * 4;
    const int b = (int)(n0 >> 17);          // / CH_STRIDE (pow2)
    const int r = (int)(n0 & 131071);       // % CH_STRIDE

    const float* xp = x + (size_t)b * BATCH_STRIDE + r;

    // x2 via streaming NEON lanes: lane[c%4] accumulates m_c in order
    // c = j, j+4, j+8, j+12 — identical rounding to sumsq16_neon.
    unsigned long long xx01[16], xx23[16];
    float l0[4], l1[4], l2[4], l3[4];
    #pragma unroll
    for (int j = 0; j < 4; j++) { l0[j] = 0.f; l1[j] = 0.f; l2[j] = 0.f; l3[j] = 0.f; }
    #pragma unroll
    for (int c = 0; c < 16; c++) {
        float4 v = *(const float4*)(xp + (size_t)c * CH_STRIDE);
        xx01[c] = pack2(v.x, v.y);
        xx23[c] = pack2(v.z, v.w);
        const int j = c & 3;
        l0[j] = add_rn(l0[j], mul_rn(v.x, v.x));   // 0 + m exact for m >= +0
        l1[j] = add_rn(l1[j], mul_rn(v.y, v.y));
        l2[j] = add_rn(l2[j], mul_rn(v.z, v.z));
        l3[j] = add_rn(l3[j], mul_rn(v.w, v.w));
    }
    const float x2_0 = add_rn(add_rn(l0[0], l0[1]), add_rn(l0[2], l0[3]));
    const float x2_1 = add_rn(add_rn(l1[0], l1[1]), add_rn(l1[2], l1[3]));
    const float x2_2 = add_rn(add_rn(l2[0], l2[1]), add_rn(l2[2], l2[3]));
    const float x2_3 = add_rn(add_rn(l3[0], l3[1]), add_rn(l3[2], l3[3]));
    const unsigned long long x2p01 = pack2(x2_0, x2_1);
    const unsigned long long x2p23 = pack2(x2_2, x2_3);
    const unsigned long long neg2  = pack2(-2.f, -2.f);

    float best0 = 3.402823466e38f, best1 = best0, best2 = best0, best3 = best0;
    int bi0 = 0, bi1 = 0, bi2 = 0, bi3 = 0;

    // encodings zero-fill: warp-cooperative, interleaved with compute.
    // Warp (global id w) owns rows [w*128, w*128+128) => 65536 floats.
    const int lane  = tid & 31;
    const int warpg = gt >> 5;
    float* ez = out + ENC_OFF + (size_t)warpg * 65536 + lane;  // 4B-aligned only

    #pragma unroll 1
    for (int j = 0; j < 256; j++) {
        const ulonglong2* ep = (const ulonglong2*)(sEb + j * 32);
        unsigned long long a0 = 0, a1 = 0, a2 = 0, a3 = 0;
        #pragma unroll
        for (int d = 0; d < 16; d++) {
            ulonglong2 e = ep[d];            // (dup(E[2j][d]), dup(E[2j+1][d]))
            a0 = fma2(xx01[d], e.x, a0);     // dot, code 2j,   pts 0,1
            a1 = fma2(xx23[d], e.x, a1);     // dot, code 2j,   pts 2,3
            a2 = fma2(xx01[d], e.y, a2);     // dot, code 2j+1, pts 0,1
            a3 = fma2(xx23[d], e.y, a3);     // dot, code 2j+1, pts 2,3
        }
        ulonglong2 e2 = ((const ulonglong2*)sE2)[j];
        // s = round(round(x2 + e2) - 2*dot)   -- replicates reference rounding
        unsigned long long s0 = fma2(neg2, a0, add2(x2p01, e2.x));
        unsigned long long s1 = fma2(neg2, a1, add2(x2p23, e2.x));
        unsigned long long s2 = fma2(neg2, a2, add2(x2p01, e2.y));
        unsigned long long s3 = fma2(neg2, a3, add2(x2p23, e2.y));

        const int k0 = 2 * j, k1 = 2 * j + 1;
        float f0, f1;
        unpack2(s0, f0, f1);
        if (f0 < best0) { best0 = f0; bi0 = k0; }
        if (f1 < best1) { best1 = f1; bi1 = k0; }
        unpack2(s1, f0, f1);
        if (f0 < best2) { best2 = f0; bi2 = k0; }
        if (f1 < best3) { best3 = f1; bi3 = k0; }
        unpack2(s2, f0, f1);
        if (f0 < best0) { best0 = f0; bi0 = k1; }
        if (f1 < best1) { best1 = f1; bi1 = k1; }
        unpack2(s3, f0, f1);
        if (f0 < best2) { best2 = f0; bi2 = k1; }
        if (f1 < best3) { best3 = f1; bi3 = k1; }

        // interleaved zero-fill: 8 x 128B coalesced streaming STG.32 per iter
        #pragma unroll
        for (int u = 0; u < 8; u++) stcs(ez + j * 256 + u * 32, 0.f);
    }

    // order zeros (cross-lane) before one-hot writes
    __syncwarp();
    {
        float* enc = out + ENC_OFF;
        stcs(enc + (size_t)(n0 + 0) * KCODES + bi0, 1.0f);
        stcs(enc + (size_t)(n0 + 1) * KCODES + bi1, 1.0f);
        stcs(enc + (size_t)(n0 + 2) * KCODES + bi2, 1.0f);
        stcs(enc + (size_t)(n0 + 3) * KCODES + bi3, 1.0f);
    }

    // ---- q_out (straight-through: x + (q - x)) + loss partial ----
    float* qbase = out + 1 + (size_t)b * BATCH_STRIDE + r;
    const float* E0 = E + bi0 * DCH;
    const float* E1 = E + bi1 * DCH;
    const float* E2 = E + bi2 * DCH;
    const float* E3 = E + bi3 * DCH;
    float ls = 0.f;
    #pragma unroll
    for (int c = 0; c < 16; c++) {
        float q0 = __ldg(E0 + c), q1 = __ldg(E1 + c), q2 = __ldg(E2 + c), q3 = __ldg(E3 + c);
        float xa, xb, xc, xd;
        unpack2(xx01[c], xa, xb);
        unpack2(xx23[c], xc, xd);
        float d0 = q0 - xa, d1 = q1 - xb, d2 = q2 - xc, d3 = q3 - xd;
        ls = fmaf(d0, d0, ls);
        ls = fmaf(d1, d1, ls);
        ls = fmaf(d2, d2, ls);
        ls = fmaf(d3, d3, ls);
        float* qo = qbase + (size_t)c * CH_STRIDE;   // 4B-aligned only -> scalar stores
        stcs(qo + 0, xa + d0);
        stcs(qo + 1, xb + d1);
        stcs(qo + 2, xc + d2);
        stcs(qo + 3, xd + d3);
    }

    // deterministic block reduction of loss partials
    sred[tid] = ls;
    __syncthreads();
    #pragma unroll
    for (int s = 128; s > 0; s >>= 1) {
        if (tid < s) sred[tid] += sred[tid + s];
        __syncthreads();
    }
    if (tid == 0) g_part[blockIdx.x] = sred[0];
}

__global__ void vq_finish_kernel(float* __restrict__ out) {
    __shared__ float sr[GRID];
    int t = threadIdx.x;
    sr[t] = g_part[t];
    __syncthreads();
    #pragma unroll
    for (int s = GRID / 2; s > 0; s >>= 1) {
        if (t < s) sr[t] += sr[t + s];
        __syncthreads();
    }
    if (t == 0) {
        float m = sr[0] / 4194304.0f;      // mean over N*D
        out[0] = m + 0.25f * m;            // q_latent + BETA * e_latent (equal forward values)
    }
}

extern "C" void kernel_launch(void* const* d_in, const int* in_sizes, int n_in,
                              void* d_out, int out_size) {
    const float* x = (const float*)d_in[0];
    const float* E = (const float*)d_in[1];
    if (n_in >= 2 && in_sizes[0] == KCODES * DCH) {  // safety if metadata order differs
        const float* t = x; x = E; E = t;
    }
    float* out = (float*)d_out;

    cudaFuncSetAttribute(vq_main_kernel,
                         cudaFuncAttributeMaxDynamicSharedMemorySize, SMEM_BYTES);
    vq_main_kernel<<<GRID, BLOCK, SMEM_BYTES>>>(x, E, out);
    vq_finish_kernel<<<1, GRID>>>(out);
}